// round 4
// baseline (speedup 1.0000x reference)
#include <cuda_runtime.h>
#include <cuda_bf16.h>

// Problem constants
#define BTOT   4096
#define DTOT   16384
#define KTOT   512
#define CCOLS  100
#define CP     112           // C padded to multiple of 8
#define EPSV   1e-4f

// Tiling
#define BM     128           // batch rows per CTA
#define BD     64            // dict rows per d-tile
#define KC     64            // k chunk
#define DSPLIT 4
#define THREADS 256
#define WARPS   8

// Shared pitches (bf16 elements) — chosen so fragment loads are conflict-free
#define XS_PITCH 520
#define KS_PITCH 72
#define VS_PITCH 72

#define SMEM_BYTES ((BM*XS_PITCH + BD*KS_PITCH + CP*VS_PITCH)*2 + BD*4)

// -------- device globals (scratch; no runtime allocation allowed) --------
__device__ __nv_bfloat16 g_xb[(size_t)BTOT * KTOT];        // 4 MB
__device__ __nv_bfloat16 g_kb[(size_t)DTOT * KTOT];        // 16 MB
__device__ __nv_bfloat16 g_vT[(size_t)CP * DTOT];          // 3.5 MB, vT[c][d]
__device__ float g_xx[BTOT];
__device__ float g_kk[DTOT];
__device__ float g_part[(size_t)DSPLIT * BTOT * CP];       // 7.3 MB partial outputs

// -------- helpers --------
__device__ __forceinline__ unsigned packbf(float lo, float hi) {
    unsigned r;
    asm("cvt.rn.bf16x2.f32 %0, %1, %2;" : "=r"(r) : "f"(hi), "f"(lo));
    return r;
}

__device__ __forceinline__ void mma16816(float (&c)[4],
                                         unsigned a0, unsigned a1, unsigned a2, unsigned a3,
                                         unsigned b0, unsigned b1) {
    asm volatile(
        "mma.sync.aligned.m16n8k16.row.col.f32.bf16.bf16.f32 "
        "{%0,%1,%2,%3}, {%4,%5,%6,%7}, {%8,%9}, {%0,%1,%2,%3};"
        : "+f"(c[0]), "+f"(c[1]), "+f"(c[2]), "+f"(c[3])
        : "r"(a0), "r"(a1), "r"(a2), "r"(a3), "r"(b0), "r"(b1));
}

// -------- prologue: per-row sum of squares + bf16 convert --------
__global__ void prep_rows(const float* __restrict__ src,
                          __nv_bfloat16* __restrict__ dst,
                          float* __restrict__ sq) {
    const int r = blockIdx.x;
    const int tid = threadIdx.x;           // 128 threads
    const float* row = src + (size_t)r * KTOT;
    __nv_bfloat16* drow = dst + (size_t)r * KTOT;
    float s = 0.f;
    #pragma unroll
    for (int c = tid; c < KTOT; c += 128) {
        float v = row[c];
        drow[c] = __float2bfloat16(v);
        s += v * v;
    }
    // warp reduce
    #pragma unroll
    for (int o = 16; o > 0; o >>= 1) s += __shfl_xor_sync(0xFFFFFFFFu, s, o);
    __shared__ float ws[4];
    if ((tid & 31) == 0) ws[tid >> 5] = s;
    __syncthreads();
    if (tid == 0) sq[r] = ws[0] + ws[1] + ws[2] + ws[3];
}

// -------- prologue: build zero-padded transposed values, bf16 --------
__global__ void prep_vT(const float* __restrict__ values) {
    const int n = CP * DTOT;
    for (int i = blockIdx.x * blockDim.x + threadIdx.x; i < n;
         i += gridDim.x * blockDim.x) {
        int c = i >> 14;          // / DTOT
        int d = i & (DTOT - 1);
        g_vT[i] = (c < CCOLS) ? __float2bfloat16(values[(size_t)d * CCOLS + c])
                              : __float2bfloat16(0.f);
    }
}

// -------- main fused kernel --------
__global__ void __launch_bounds__(THREADS, 1)
varkeys_main() {
    extern __shared__ __align__(16) char smem_raw[];
    __nv_bfloat16* xs = (__nv_bfloat16*)smem_raw;             // [BM][XS_PITCH]
    __nv_bfloat16* ks = xs + BM * XS_PITCH;                   // [BD][KS_PITCH]
    __nv_bfloat16* vs = ks + BD * KS_PITCH;                   // [CP][VS_PITCH]
    float* kks = (float*)(vs + CP * VS_PITCH);                // [BD]

    const int tid  = threadIdx.x;
    const int warp = tid >> 5;
    const int lane = tid & 31;
    const int g = lane >> 2;      // 0..7
    const int t = lane & 3;       // 0..3
    const int bm0 = blockIdx.x * BM;
    const int d0  = blockIdx.y * (DTOT / DSPLIT);

    // Load full x tile [BM][KTOT] into SMEM once (resident whole kernel)
    for (int i = tid; i < BM * (KTOT / 8); i += THREADS) {
        int r = i >> 6;                 // KTOT/8 = 64
        int c8 = i & 63;
        *(uint4*)(xs + r * XS_PITCH + c8 * 8) =
            *(const uint4*)(g_xb + (size_t)(bm0 + r) * KTOT + c8 * 8);
    }

    const float xx0 = g_xx[bm0 + warp * 16 + g];
    const float xx1 = g_xx[bm0 + warp * 16 + 8 + g];

    float oacc[14][4];
    #pragma unroll
    for (int i = 0; i < 14; ++i)
        #pragma unroll
        for (int j = 0; j < 4; ++j) oacc[i][j] = 0.f;

    __syncthreads();

    const __nv_bfloat16* xrow0 = xs + (warp * 16 + g) * XS_PITCH + 2 * t;
    const __nv_bfloat16* xrow1 = xrow0 + 8 * XS_PITCH;

    for (int dt = 0; dt < (DTOT / DSPLIT) / BD; ++dt) {
        const int db = d0 + dt * BD;

        __syncthreads();  // prior reads of vs/kks done before overwrite
        // load vT tile [CP][BD]
        for (int i = tid; i < CP * (BD / 8); i += THREADS) {   // 896
            int r = i >> 3, c8 = i & 7;
            *(uint4*)(vs + r * VS_PITCH + c8 * 8) =
                *(const uint4*)(g_vT + (size_t)r * DTOT + db + c8 * 8);
        }
        if (tid < BD) kks[tid] = g_kk[db + tid];

        float sacc[8][4];
        #pragma unroll
        for (int i = 0; i < 8; ++i)
            #pragma unroll
            for (int j = 0; j < 4; ++j) sacc[i][j] = 0.f;

        // GEMM1: S[BM x BD] over K=512 in chunks of 64
        for (int kc = 0; kc < KTOT / KC; ++kc) {
            __syncthreads();   // prior ks reads done; (kc==0) makes vs/kks visible
            for (int i = tid; i < BD * (KC / 8); i += THREADS) {  // 512
                int r = i >> 3, c8 = i & 7;
                *(uint4*)(ks + r * KS_PITCH + c8 * 8) =
                    *(const uint4*)(g_kb + (size_t)(db + r) * KTOT + kc * KC + c8 * 8);
            }
            __syncthreads();
            #pragma unroll
            for (int kst = 0; kst < 4; ++kst) {
                const int xc = kc * KC + kst * 16;
                unsigned a0 = *(const unsigned*)(xrow0 + xc);
                unsigned a2 = *(const unsigned*)(xrow0 + xc + 8);
                unsigned a1 = *(const unsigned*)(xrow1 + xc);
                unsigned a3 = *(const unsigned*)(xrow1 + xc + 8);
                #pragma unroll
                for (int nt = 0; nt < 8; ++nt) {
                    const __nv_bfloat16* bp =
                        ks + (nt * 8 + g) * KS_PITCH + kst * 16 + 2 * t;
                    unsigned b0 = *(const unsigned*)bp;
                    unsigned b1 = *(const unsigned*)(bp + 8);
                    mma16816(sacc[nt], a0, a1, a2, a3, b0, b1);
                }
            }
        }

        // Elementwise: kern = 1/(xx + kk - 2s + eps), convert in-register to
        // GEMM2 A-fragments (C-frag layout == A-frag layout, the FA trick).
        unsigned alo[8], ahi[8];
        #pragma unroll
        for (int nt = 0; nt < 8; ++nt) {
            float kk0 = kks[nt * 8 + 2 * t];
            float kk1 = kks[nt * 8 + 2 * t + 1];
            float r0 = __frcp_rn(xx0 + kk0 - 2.f * sacc[nt][0] + EPSV);
            float r1 = __frcp_rn(xx0 + kk1 - 2.f * sacc[nt][1] + EPSV);
            float r2 = __frcp_rn(xx1 + kk0 - 2.f * sacc[nt][2] + EPSV);
            float r3 = __frcp_rn(xx1 + kk1 - 2.f * sacc[nt][3] + EPSV);
            alo[nt] = packbf(r0, r1);
            ahi[nt] = packbf(r2, r3);
        }

        // GEMM2: out[BM x CP] += kern[BM x BD] @ vT^T  (K = BD = 64, 4 k-steps)
        #pragma unroll
        for (int kst = 0; kst < 4; ++kst) {
            unsigned a0 = alo[2 * kst];
            unsigned a1 = ahi[2 * kst];
            unsigned a2 = alo[2 * kst + 1];
            unsigned a3 = ahi[2 * kst + 1];
            #pragma unroll
            for (int nt2 = 0; nt2 < 14; ++nt2) {
                const __nv_bfloat16* bp =
                    vs + (nt2 * 8 + g) * VS_PITCH + kst * 16 + 2 * t;
                unsigned b0 = *(const unsigned*)bp;
                unsigned b1 = *(const unsigned*)(bp + 8);
                mma16816(oacc[nt2], a0, a1, a2, a3, b0, b1);
            }
        }
    }

    // Write deterministic per-split partials (full CP coverage, no atomics)
    const int m0 = bm0 + warp * 16 + g;
    float* p0 = g_part + ((size_t)blockIdx.y * BTOT + m0) * CP;
    float* p1 = p0 + 8 * CP;
    #pragma unroll
    for (int nt2 = 0; nt2 < 14; ++nt2) {
        int c0 = nt2 * 8 + 2 * t;
        p0[c0]     = oacc[nt2][0];
        p0[c0 + 1] = oacc[nt2][1];
        p1[c0]     = oacc[nt2][2];
        p1[c0 + 1] = oacc[nt2][3];
    }
}

// -------- final reduce over D-splits --------
__global__ void reduce_out(float* __restrict__ out) {
    int i = blockIdx.x * blockDim.x + threadIdx.x;
    if (i < BTOT * CCOLS) {
        int m = i / CCOLS;
        int c = i - m * CCOLS;
        float s = 0.f;
        #pragma unroll
        for (int ds = 0; ds < DSPLIT; ++ds)
            s += g_part[((size_t)ds * BTOT + m) * CP + c];
        out[i] = s;
    }
}

extern "C" void kernel_launch(void* const* d_in, const int* in_sizes, int n_in,
                              void* d_out, int out_size) {
    const float* x      = (const float*)d_in[0];   // (4096, 512)
    const float* keys   = (const float*)d_in[1];   // (16384, 512)
    const float* values = (const float*)d_in[2];   // (16384, 100)
    float* out = (float*)d_out;                    // (4096, 100)
    (void)in_sizes; (void)n_in; (void)out_size;

    // Prologue
    {
        __nv_bfloat16 *xb_p, *kb_p;
        float *xx_p, *kk_p;
        cudaGetSymbolAddress((void**)&xb_p, g_xb);
        cudaGetSymbolAddress((void**)&kb_p, g_kb);
        cudaGetSymbolAddress((void**)&xx_p, g_xx);
        cudaGetSymbolAddress((void**)&kk_p, g_kk);
        prep_rows<<<BTOT, 128>>>(x, xb_p, xx_p);
        prep_rows<<<DTOT, 128>>>(keys, kb_p, kk_p);
        prep_vT<<<2048, 256>>>(values);
    }

    // Main fused kernel
    static_assert(SMEM_BYTES < 227 * 1024, "smem too big");
    cudaFuncSetAttribute(varkeys_main,
                         cudaFuncAttributeMaxDynamicSharedMemorySize, SMEM_BYTES);
    dim3 grid(BTOT / BM, DSPLIT);
    varkeys_main<<<grid, THREADS, SMEM_BYTES>>>();

    // Reduce
    reduce_out<<<(BTOT * CCOLS + 255) / 256, 256>>>(out);
}

// round 6
// speedup vs baseline: 2.3277x; 2.3277x over previous
#include <cuda_runtime.h>
#include <cuda_bf16.h>
#include <cstdint>

// Problem constants
#define BTOT   4096
#define DTOT   16384
#define KTOT   512
#define CCOLS  100
#define CP     104           // C padded to 13 n8 tiles
#define NCT    13
#define EPSV   1e-4f

// Tiling
#define BM     128
#define BD     64
#define KC     64
#define NKC    8             // KTOT/KC
#define DSPLIT 4
#define NTILES 64            // DTOT/DSPLIT/BD
#define THREADS 512

// Shared pitches (bf16 elements)
#define XS_PITCH 520
#define KS_PITCH 72
#define VS_PITCH 72
#define KS_BUF_EL (BD * KS_PITCH)
#define NKBUF 3

#define SMEM_BYTES ((BM*XS_PITCH + NKBUF*KS_BUF_EL + CP*VS_PITCH) * 2)

// -------- device globals --------
__device__ __nv_bfloat16 g_xb[(size_t)BTOT * KTOT];
__device__ __nv_bfloat16 g_kb[(size_t)DTOT * KTOT];
__device__ __nv_bfloat16 g_vT[(size_t)CP * DTOT];          // vT[c][d]
__device__ float g_xx[BTOT];
__device__ float g_kk[DTOT];
__device__ float g_part[(size_t)DSPLIT * BTOT * CP];

// -------- helpers --------
__device__ __forceinline__ unsigned packbf(float lo, float hi) {
    unsigned r;
    asm("cvt.rn.bf16x2.f32 %0, %1, %2;" : "=r"(r) : "f"(hi), "f"(lo));
    return r;
}
__device__ __forceinline__ float rcpa(float x) {
    float r;
    asm("rcp.approx.f32 %0, %1;" : "=f"(r) : "f"(x));
    return r;
}
__device__ __forceinline__ void mma16816(float (&c)[4],
                                         unsigned a0, unsigned a1, unsigned a2, unsigned a3,
                                         unsigned b0, unsigned b1) {
    asm volatile(
        "mma.sync.aligned.m16n8k16.row.col.f32.bf16.bf16.f32 "
        "{%0,%1,%2,%3}, {%4,%5,%6,%7}, {%8,%9}, {%0,%1,%2,%3};"
        : "+f"(c[0]), "+f"(c[1]), "+f"(c[2]), "+f"(c[3])
        : "r"(a0), "r"(a1), "r"(a2), "r"(a3), "r"(b0), "r"(b1));
}
__device__ __forceinline__ void ldsm4(unsigned &r0, unsigned &r1, unsigned &r2, unsigned &r3,
                                      uint32_t addr) {
    asm volatile("ldmatrix.sync.aligned.m8n8.x4.shared.b16 {%0,%1,%2,%3}, [%4];"
        : "=r"(r0), "=r"(r1), "=r"(r2), "=r"(r3) : "r"(addr));
}
__device__ __forceinline__ void ldsm2(unsigned &r0, unsigned &r1, uint32_t addr) {
    asm volatile("ldmatrix.sync.aligned.m8n8.x2.shared.b16 {%0,%1}, [%2];"
        : "=r"(r0), "=r"(r1) : "r"(addr));
}
__device__ __forceinline__ void cpa16(uint32_t dst, const void* src) {
    asm volatile("cp.async.cg.shared.global [%0], [%1], 16;" :: "r"(dst), "l"(src));
}
#define CP_COMMIT() asm volatile("cp.async.commit_group;")

// -------- prologue: per-row sum of squares + bf16 convert --------
__global__ void prep_rows(const float* __restrict__ src,
                          __nv_bfloat16* __restrict__ dst,
                          float* __restrict__ sq) {
    const int r = blockIdx.x;
    const int tid = threadIdx.x;           // 128 threads
    const float* row = src + (size_t)r * KTOT;
    __nv_bfloat16* drow = dst + (size_t)r * KTOT;
    float s = 0.f;
    #pragma unroll
    for (int c = tid; c < KTOT; c += 128) {
        float v = row[c];
        drow[c] = __float2bfloat16(v);
        s += v * v;
    }
    #pragma unroll
    for (int o = 16; o > 0; o >>= 1) s += __shfl_xor_sync(0xFFFFFFFFu, s, o);
    __shared__ float ws[4];
    if ((tid & 31) == 0) ws[tid >> 5] = s;
    __syncthreads();
    if (tid == 0) sq[r] = ws[0] + ws[1] + ws[2] + ws[3];
}

// -------- prologue: zero-padded transposed values, bf16 --------
__global__ void prep_vT(const float* __restrict__ values) {
    const int n = CP * DTOT;
    for (int i = blockIdx.x * blockDim.x + threadIdx.x; i < n;
         i += gridDim.x * blockDim.x) {
        int c = i >> 14;          // / DTOT
        int d = i & (DTOT - 1);
        g_vT[i] = (c < CCOLS) ? __float2bfloat16(values[(size_t)d * CCOLS + c])
                              : __float2bfloat16(0.f);
    }
}

// -------- main fused kernel --------
__global__ void __launch_bounds__(THREADS, 1)
varkeys_main() {
    extern __shared__ __align__(16) char smem_raw[];
    __nv_bfloat16* xs = (__nv_bfloat16*)smem_raw;          // [BM][XS_PITCH]
    __nv_bfloat16* ks = xs + BM * XS_PITCH;                // [3][BD][KS_PITCH]
    __nv_bfloat16* vs = ks + NKBUF * KS_BUF_EL;            // [CP][VS_PITCH]

    const int tid  = threadIdx.x;
    const int warp = tid >> 5;
    const int lane = tid & 31;
    const int g = lane >> 2;
    const int t = lane & 3;
    const int wm = warp & 7;      // M warp-group (16 rows)
    const int wd = warp >> 3;     // D half (32 cols of BD)
    const int bm0 = blockIdx.x * BM;
    const int d0  = blockIdx.y * (DTOT / DSPLIT);

    const uint32_t xs_u = (uint32_t)__cvta_generic_to_shared(xs);
    const uint32_t ks_u = (uint32_t)__cvta_generic_to_shared(ks);
    const uint32_t vs_u = (uint32_t)__cvta_generic_to_shared(vs);

    // ldmatrix per-lane offsets (elements)
    const int aoff  = ((lane & 7) + ((lane >> 3) & 1) * 8) * XS_PITCH + ((lane >> 4) & 1) * 8;
    const int koff  = ((lane & 7) + ((lane >> 4) & 1) * 8) * KS_PITCH + ((lane >> 3) & 1) * 8;
    const int voff4 = ((lane & 7) + ((lane >> 4) & 1) * 8) * VS_PITCH + ((lane >> 3) & 1) * 8;
    const int l2    = lane & 15;
    const int voff2 = (l2 & 7) * VS_PITCH + ((l2 >> 3) & 1) * 8;

    const uint32_t xa_base  = xs_u + (uint32_t)(wm * 16 * XS_PITCH + aoff) * 2;
    const uint32_t kb_lane  = (uint32_t)(wd * 32 * KS_PITCH + koff) * 2;
    const uint32_t vb4_base = vs_u + (uint32_t)(voff4 + wd * 32) * 2;
    const uint32_t vb2_base = vs_u + (uint32_t)(voff2 + 96 * VS_PITCH + wd * 32) * 2;

    // cp.async issue helpers
    auto issue_ks = [&](int buf, int db_, int kc_) {
        int r = tid >> 3, c = tid & 7;     // 512 threads == 64 rows x 8 chunks
        uint32_t dst = ks_u + (uint32_t)(buf * KS_BUF_EL + r * KS_PITCH + c * 8) * 2;
        cpa16(dst, g_kb + (size_t)(db_ + r) * KTOT + kc_ * KC + c * 8);
        CP_COMMIT();
    };
    auto issue_vs = [&](int db_) {
        #pragma unroll
        for (int i = tid; i < CP * 8; i += THREADS) {
            int r = i >> 3, c = i & 7;
            uint32_t dst = vs_u + (uint32_t)(r * VS_PITCH + c * 8) * 2;
            cpa16(dst, g_vT + (size_t)r * DTOT + db_ + c * 8);
        }
        CP_COMMIT();
    };

    // group 1: xs (resident for whole kernel)
    #pragma unroll 4
    for (int i = tid; i < BM * (KTOT / 8); i += THREADS) {
        int r = i >> 6, c = i & 63;
        cpa16(xs_u + (uint32_t)(r * XS_PITCH + c * 8) * 2,
              g_xb + (size_t)(bm0 + r) * KTOT + c * 8);
    }
    CP_COMMIT();
    issue_ks(0, d0, 0);   // group 2
    issue_ks(1, d0, 1);   // group 3
    issue_vs(d0);         // group 4

    const float xx0 = g_xx[bm0 + wm * 16 + g];
    const float xx1 = g_xx[bm0 + wm * 16 + 8 + g];

    float oacc[NCT][4];
    #pragma unroll
    for (int i = 0; i < NCT; ++i)
        #pragma unroll
        for (int j = 0; j < 4; ++j) oacc[i][j] = 0.f;

    #pragma unroll 1
    for (int dt = 0; dt < NTILES; ++dt) {
        const int db = d0 + dt * BD;

        // prefetch kk for the epilogue (hidden behind GEMM1)
        float2 kkp[4];
        #pragma unroll
        for (int nt = 0; nt < 4; ++nt)
            kkp[nt] = *(const float2*)&g_kk[db + wd * 32 + nt * 8 + 2 * t];

        float sacc[4][4];
        #pragma unroll
        for (int i = 0; i < 4; ++i)
            #pragma unroll
            for (int j = 0; j < 4; ++j) sacc[i][j] = 0.f;

        // GEMM1: S[BM x BD] over K=512 (8 chunks, 3-stage cp.async pipeline)
        #pragma unroll
        for (int kc = 0; kc < NKC; ++kc) {
            // steady-state group order per tile: [ks0, ks1, vs, ks2..ks7]
            if (kc < 2)      asm volatile("cp.async.wait_group 2;");
            else if (kc < 7) asm volatile("cp.async.wait_group 1;");
            else             asm volatile("cp.async.wait_group 0;");
            __syncthreads();                          // visibility + reuse safety
            if (kc + 2 < NKC) issue_ks((kc + 2) % 3, db, kc + 2);

            const uint32_t ksb = ks_u + (uint32_t)((kc % 3) * KS_BUF_EL) * 2 + kb_lane;
            #pragma unroll
            for (int kst = 0; kst < 4; ++kst) {
                unsigned a0, a1, a2, a3;
                ldsm4(a0, a1, a2, a3, xa_base + (uint32_t)(kc * KC + kst * 16) * 2);
                #pragma unroll
                for (int p = 0; p < 2; ++p) {
                    unsigned b0, b1, b2, b3;
                    ldsm4(b0, b1, b2, b3,
                          ksb + (uint32_t)(p * 16 * KS_PITCH + kst * 16) * 2);
                    mma16816(sacc[2 * p],     a0, a1, a2, a3, b0, b1);
                    mma16816(sacc[2 * p + 1], a0, a1, a2, a3, b2, b3);
                }
            }
        }

        // kern = 1/(xx + kk - 2s + eps) -> bf16 A-fragments (register-only)
        unsigned alo[4], ahi[4];
        #pragma unroll
        for (int nt = 0; nt < 4; ++nt) {
            float kk0 = kkp[nt].x, kk1 = kkp[nt].y;
            float r0 = rcpa(xx0 + kk0 - 2.f * sacc[nt][0] + EPSV);
            float r1 = rcpa(xx0 + kk1 - 2.f * sacc[nt][1] + EPSV);
            float r2 = rcpa(xx1 + kk0 - 2.f * sacc[nt][2] + EPSV);
            float r3 = rcpa(xx1 + kk1 - 2.f * sacc[nt][3] + EPSV);
            alo[nt] = packbf(r0, r1);
            ahi[nt] = packbf(r2, r3);
        }

        __syncthreads();   // A: all warps done with ks buffers
        if (dt + 1 < NTILES) { issue_ks(0, db + BD, 0); issue_ks(1, db + BD, 1); }

        // GEMM2: out[BM x CP] += kern[BM x 32(wd)] @ vT  (K=32 per warp)
        #pragma unroll
        for (int k2 = 0; k2 < 2; ++k2) {
            unsigned a0 = alo[2 * k2], a1 = ahi[2 * k2];
            unsigned a2 = alo[2 * k2 + 1], a3 = ahi[2 * k2 + 1];
            #pragma unroll
            for (int j = 0; j < 6; ++j) {
                unsigned b0, b1, b2, b3;
                ldsm4(b0, b1, b2, b3,
                      vb4_base + (uint32_t)(j * 16 * VS_PITCH + k2 * 16) * 2);
                mma16816(oacc[2 * j],     a0, a1, a2, a3, b0, b1);
                mma16816(oacc[2 * j + 1], a0, a1, a2, a3, b2, b3);
            }
            unsigned b0, b1;
            ldsm2(b0, b1, vb2_base + (uint32_t)(k2 * 16) * 2);
            mma16816(oacc[12], a0, a1, a2, a3, b0, b1);
        }

        __syncthreads();   // B: all warps done with vs
        if (dt + 1 < NTILES) issue_vs(db + BD);
    }

    // cross-warp (wd) reduction via smem (reuse xs region), then write partials
    float* red = (float*)smem_raw;
    const int rbase = (wm * 32 + lane) * 53;     // pitch 53: conflict-free
    if (wd == 1) {
        #pragma unroll
        for (int i = 0; i < NCT; ++i)
            #pragma unroll
            for (int j = 0; j < 4; ++j) red[rbase + i * 4 + j] = oacc[i][j];
    }
    __syncthreads();
    if (wd == 0) {
        #pragma unroll
        for (int i = 0; i < NCT; ++i)
            #pragma unroll
            for (int j = 0; j < 4; ++j) oacc[i][j] += red[rbase + i * 4 + j];
        const int m0 = bm0 + wm * 16 + g;
        float* p0 = g_part + ((size_t)blockIdx.y * BTOT + m0) * CP;
        float* p1 = p0 + 8 * CP;
        #pragma unroll
        for (int nt2 = 0; nt2 < NCT; ++nt2) {
            int c0 = nt2 * 8 + 2 * t;
            p0[c0]     = oacc[nt2][0];
            p0[c0 + 1] = oacc[nt2][1];
            p1[c0]     = oacc[nt2][2];
            p1[c0 + 1] = oacc[nt2][3];
        }
    }
}

// -------- final reduce over D-splits --------
__global__ void reduce_out(float* __restrict__ out) {
    int i = blockIdx.x * blockDim.x + threadIdx.x;
    if (i < BTOT * CCOLS) {
        int m = i / CCOLS;
        int c = i - m * CCOLS;
        float s = 0.f;
        #pragma unroll
        for (int ds = 0; ds < DSPLIT; ++ds)
            s += g_part[((size_t)ds * BTOT + m) * CP + c];
        out[i] = s;
    }
}

extern "C" void kernel_launch(void* const* d_in, const int* in_sizes, int n_in,
                              void* d_out, int out_size) {
    const float* x      = (const float*)d_in[0];   // (4096, 512)
    const float* keys   = (const float*)d_in[1];   // (16384, 512)
    const float* values = (const float*)d_in[2];   // (16384, 100)
    float* out = (float*)d_out;                    // (4096, 100)
    (void)in_sizes; (void)n_in; (void)out_size;

    {
        __nv_bfloat16 *xb_p, *kb_p;
        float *xx_p, *kk_p;
        cudaGetSymbolAddress((void**)&xb_p, g_xb);
        cudaGetSymbolAddress((void**)&kb_p, g_kb);
        cudaGetSymbolAddress((void**)&xx_p, g_xx);
        cudaGetSymbolAddress((void**)&kk_p, g_kk);
        prep_rows<<<BTOT, 128>>>(x, xb_p, xx_p);
        prep_rows<<<DTOT, 128>>>(keys, kb_p, kk_p);
        prep_vT<<<2048, 256>>>(values);
    }

    static_assert(SMEM_BYTES < 227 * 1024, "smem too big");
    cudaFuncSetAttribute(varkeys_main,
                         cudaFuncAttributeMaxDynamicSharedMemorySize, SMEM_BYTES);
    dim3 grid(BTOT / BM, DSPLIT);
    varkeys_main<<<grid, THREADS, SMEM_BYTES>>>();

    reduce_out<<<(BTOT * CCOLS + 255) / 256, 256>>>(out);
}

// round 9
// speedup vs baseline: 2.8789x; 1.2368x over previous
#include <cuda_runtime.h>
#include <cuda.h>
#include <cuda_bf16.h>
#include <cstdint>
#include <dlfcn.h>

// Problem constants
#define BTOT   4096
#define DTOT   16384
#define KTOT   512
#define CCOLS  100
#define CP     104            // padded C (13 x n8)
#define EPSV   1e-4f

// Tiling
#define BM     128            // batch rows per CTA
#define BD     64             // keys per tile
#define DSPLIT 4
#define NT     64             // tiles per CTA
#define THREADS 256           // 8 warps: wm(4) x wd(2), M32 x N32 each

// SMEM offsets (from 1024-aligned base)
#define XS_OFF 0              // 8 chunks x [128 rows x 128B] SW128   131072
#define KS_OFF 131072         // 4 pair-buffers x 16KB                 65536
#define VS_OFF 196608         // 2 x [104 rows x 128B]                 26624
#define KK_OFF 223232         // 2 x 256B                                512
#define MB_OFF 223744         // mbarriers
#define SMEM_BYTES (223808 + 1024)

// -------- device globals --------
__device__ __align__(128) __nv_bfloat16 g_xb[(size_t)BTOT * KTOT];
__device__ __align__(128) __nv_bfloat16 g_kb[(size_t)DTOT * KTOT];
__device__ __align__(128) __nv_bfloat16 g_vT[(size_t)CP * DTOT];   // vT[c][d]
__device__ __align__(128) float g_xx[BTOT];
__device__ __align__(128) float g_kk[DTOT];
__device__ __align__(128) float g_part[(size_t)DSPLIT * BTOT * CP];

// -------- helpers --------
static __device__ __forceinline__ uint32_t sw128(uint32_t off) {
    return off ^ ((off >> 3) & 0x70);
}
static __device__ __forceinline__ unsigned packbf(float lo, float hi) {
    unsigned r;
    asm("cvt.rn.bf16x2.f32 %0, %1, %2;" : "=r"(r) : "f"(hi), "f"(lo));
    return r;
}
static __device__ __forceinline__ float rcpa(float x) {
    float r; asm("rcp.approx.f32 %0, %1;" : "=f"(r) : "f"(x)); return r;
}
static __device__ __forceinline__ void mma16816(float (&c)[4],
        unsigned a0, unsigned a1, unsigned a2, unsigned a3,
        unsigned b0, unsigned b1) {
    asm volatile(
        "mma.sync.aligned.m16n8k16.row.col.f32.bf16.bf16.f32 "
        "{%0,%1,%2,%3}, {%4,%5,%6,%7}, {%8,%9}, {%0,%1,%2,%3};"
        : "+f"(c[0]), "+f"(c[1]), "+f"(c[2]), "+f"(c[3])
        : "r"(a0), "r"(a1), "r"(a2), "r"(a3), "r"(b0), "r"(b1));
}
static __device__ __forceinline__ void ldsm4(unsigned &r0, unsigned &r1,
        unsigned &r2, unsigned &r3, uint32_t addr) {
    asm volatile("ldmatrix.sync.aligned.m8n8.x4.shared.b16 {%0,%1,%2,%3}, [%4];"
        : "=r"(r0), "=r"(r1), "=r"(r2), "=r"(r3) : "r"(addr));
}
static __device__ __forceinline__ void ldsm2(unsigned &r0, unsigned &r1, uint32_t addr) {
    asm volatile("ldmatrix.sync.aligned.m8n8.x2.shared.b16 {%0,%1}, [%2];"
        : "=r"(r0), "=r"(r1) : "r"(addr));
}
static __device__ __forceinline__ void tma2d(uint32_t dst, const void* map,
                                             int cx, int cy, uint32_t mbar) {
    asm volatile(
        "cp.async.bulk.tensor.2d.shared::cluster.global.tile.mbarrier::complete_tx::bytes "
        "[%0], [%1, {%2, %3}], [%4];"
        :: "r"(dst), "l"(map), "r"(cx), "r"(cy), "r"(mbar) : "memory");
}
static __device__ __forceinline__ void bulk1d(uint32_t dst, const void* src,
                                              uint32_t bytes, uint32_t mbar) {
    asm volatile(
        "cp.async.bulk.shared::cluster.global.mbarrier::complete_tx::bytes "
        "[%0], [%1], %2, [%3];"
        :: "r"(dst), "l"(src), "r"(bytes), "r"(mbar) : "memory");
}
#define MB_INIT(mb, n) asm volatile("mbarrier.init.shared.b64 [%0], %1;" \
    :: "r"(mb), "r"((uint32_t)(n)) : "memory")
#define MB_EXPECT_TX(mb, tx) asm volatile( \
    "mbarrier.arrive.expect_tx.shared.b64 _, [%0], %1;" \
    :: "r"(mb), "r"((uint32_t)(tx)) : "memory")
static __device__ __forceinline__ void mb_wait(uint32_t mb, uint32_t parity) {
    asm volatile("{\n\t.reg .pred P1;\n\t"
        "WL_%=:\n\t"
        "mbarrier.try_wait.parity.acquire.cta.shared::cta.b64 P1, [%0], %1, 0x989680;\n\t"
        "@P1 bra.uni WD_%=;\n\t"
        "bra.uni WL_%=;\n\t"
        "WD_%=:\n\t}" :: "r"(mb), "r"(parity) : "memory");
}

// -------- prologue kernels --------
__global__ void prep_rows(const float* __restrict__ src,
                          __nv_bfloat16* __restrict__ dst,
                          float* __restrict__ sq) {
    const int r = blockIdx.x;
    const int tid = threadIdx.x;           // 128
    const float* row = src + (size_t)r * KTOT;
    __nv_bfloat16* drow = dst + (size_t)r * KTOT;
    float s = 0.f;
    #pragma unroll
    for (int c = tid; c < KTOT; c += 128) {
        float v = row[c];
        drow[c] = __float2bfloat16(v);
        s += v * v;
    }
    #pragma unroll
    for (int o = 16; o > 0; o >>= 1) s += __shfl_xor_sync(0xFFFFFFFFu, s, o);
    __shared__ float ws[4];
    if ((tid & 31) == 0) ws[tid >> 5] = s;
    __syncthreads();
    if (tid == 0) sq[r] = ws[0] + ws[1] + ws[2] + ws[3];
}

__global__ void prep_vT(const float* __restrict__ values) {
    const int n = CP * DTOT;
    for (int i = blockIdx.x * blockDim.x + threadIdx.x; i < n;
         i += gridDim.x * blockDim.x) {
        int c = i >> 14;          // / DTOT
        int d = i & (DTOT - 1);
        g_vT[i] = (c < CCOLS) ? __float2bfloat16(values[(size_t)d * CCOLS + c])
                              : __float2bfloat16(0.f);
    }
}

// -------- main fused kernel --------
__global__ void __launch_bounds__(THREADS, 1)
varkeys_main(const __grid_constant__ CUtensorMap tmx,
             const __grid_constant__ CUtensorMap tmk,
             const __grid_constant__ CUtensorMap tmv) {
    extern __shared__ __align__(16) char smem_raw[];
    char* smb = (char*)((((uintptr_t)smem_raw) + 1023) & ~(uintptr_t)1023);
    uint32_t su;
    asm("{ .reg .u64 t; cvta.to.shared.u64 t, %1; cvt.u32.u64 %0, t; }"
        : "=r"(su) : "l"(smb));

    const int tid  = threadIdx.x;
    const int warp = tid >> 5;
    const int lane = tid & 31;
    const int g = lane >> 2;
    const int t = lane & 3;
    const int wm = warp & 3;       // M group: rows [wm*32, wm*32+32)
    const int wd = warp >> 2;      // N/k half: cols [wd*32, wd*32+32)
    const int bm0 = blockIdx.x * BM;
    const int d0  = blockIdx.y * (DTOT / DSPLIT);

    const uint32_t mb_xs = su + MB_OFF;
    const uint32_t mb_ks = su + MB_OFF + 8;    // [4]
    const uint32_t mb_vs = su + MB_OFF + 48;   // [2]

    if (tid == 0) {
        MB_INIT(mb_xs, 1);
        #pragma unroll
        for (int p = 0; p < 4; ++p) MB_INIT(mb_ks + p * 8, 1);
        MB_INIT(mb_vs, 1); MB_INIT(mb_vs + 8, 1);
    }
    __syncthreads();

    if (tid == 0) {
        // xs: 8 chunk TMAs, one barrier
        MB_EXPECT_TX(mb_xs, 131072);
        #pragma unroll
        for (int c = 0; c < 8; ++c)
            tma2d(su + XS_OFF + c * 16384, &tmx, c * 64, bm0, mb_xs);
        // vs + kk for tiles 0,1
        #pragma unroll
        for (int i = 0; i < 2; ++i) {
            MB_EXPECT_TX(mb_vs + i * 8, 13312 + 256);
            tma2d(su + VS_OFF + i * 13312, &tmv, d0 + i * BD, 0, mb_vs + i * 8);
            bulk1d(su + KK_OFF + i * 256, g_kk + d0 + i * BD, 256, mb_vs + i * 8);
        }
        // ks pairs for tile 0
        #pragma unroll
        for (int p = 0; p < 4; ++p) {
            MB_EXPECT_TX(mb_ks + p * 8, 16384);
            tma2d(su + KS_OFF + p * 16384,        &tmk, (2 * p) * 64,     d0, mb_ks + p * 8);
            tma2d(su + KS_OFF + p * 16384 + 8192, &tmk, (2 * p + 1) * 64, d0, mb_ks + p * 8);
        }
    }

    // ---- per-lane ldmatrix offsets ----
    const int ar = (lane & 7) + ((lane >> 3) & 1) * 8;    // A row-in-16
    const int ak = (lane >> 4) & 1;                        // A k 16B half
    const uint32_t aoff0 = (uint32_t)(wm * 4 + (ar >> 3)) * 1024u;
    uint32_t asw[4];
    #pragma unroll
    for (int k = 0; k < 4; ++k)
        asw[k] = sw128((uint32_t)((ar & 7) * 128 + k * 32 + ak * 16));

    const int br = (lane & 7) + ((lane >> 4) & 1) * 8;    // B row-in-16 (n)
    const int bk = (lane >> 3) & 1;
    const uint32_t boff0 = (uint32_t)(wd * 4 + (br >> 3)) * 1024u;
    uint32_t bsw[4];
    #pragma unroll
    for (int k = 0; k < 4; ++k)
        bsw[k] = sw128((uint32_t)((br & 7) * 128 + k * 32 + bk * 16));

    uint32_t voff[6];
    #pragma unroll
    for (int j2 = 0; j2 < 6; ++j2) voff[j2] = (uint32_t)(j2 * 2 + (br >> 3)) * 1024u;
    uint32_t vsw[2], v2sw[2];
    const int l15 = lane & 15;
    #pragma unroll
    for (int k2 = 0; k2 < 2; ++k2) {
        vsw[k2]  = sw128((uint32_t)((br & 7) * 128 + wd * 64 + k2 * 32 + bk * 16));
        v2sw[k2] = sw128((uint32_t)((l15 & 7) * 128 + wd * 64 + k2 * 32 + ((l15 >> 3) & 1) * 16));
    }

    // xx (+eps folded)
    float xxe[2][2];
    #pragma unroll
    for (int mh = 0; mh < 2; ++mh) {
        xxe[mh][0] = g_xx[bm0 + wm * 32 + mh * 16 + g]     + EPSV;
        xxe[mh][1] = g_xx[bm0 + wm * 32 + mh * 16 + 8 + g] + EPSV;
    }

    float oacc[2][13][4];
    #pragma unroll
    for (int mh = 0; mh < 2; ++mh)
        #pragma unroll
        for (int j = 0; j < 13; ++j)
            #pragma unroll
            for (int q = 0; q < 4; ++q) oacc[mh][j][q] = 0.f;

    mb_wait(mb_xs, 0);   // xs resident from here on

    #pragma unroll 1
    for (int dt = 0; dt < NT; ++dt) {
        const uint32_t par  = (uint32_t)(dt & 1);
        const int cur = dt & 1;
        const uint32_t pvs  = (uint32_t)((dt >> 1) & 1);

        float sacc[2][4][4];
        #pragma unroll
        for (int mh = 0; mh < 2; ++mh)
            #pragma unroll
            for (int nt = 0; nt < 4; ++nt)
                #pragma unroll
                for (int q = 0; q < 4; ++q) sacc[mh][nt][q] = 0.f;

        // ---- GEMM1: S[128x64] over K=512, 4 pair-buffers ----
        #pragma unroll
        for (int p = 0; p < 4; ++p) {
            mb_wait(mb_ks + p * 8, par);
            #pragma unroll
            for (int q = 0; q < 2; ++q) {
                const uint32_t ab = su + XS_OFF + (2 * p + q) * 16384 + aoff0;
                const uint32_t bb = su + KS_OFF + p * 16384 + q * 8192 + boff0;
                #pragma unroll
                for (int kst = 0; kst < 4; ++kst) {
                    unsigned a0,a1,a2,a3, a4,a5,a6,a7;
                    ldsm4(a0,a1,a2,a3, ab + asw[kst]);
                    ldsm4(a4,a5,a6,a7, ab + 2048 + asw[kst]);
                    unsigned b0,b1,b2,b3, b4,b5,b6,b7;
                    ldsm4(b0,b1,b2,b3, bb + bsw[kst]);
                    ldsm4(b4,b5,b6,b7, bb + 2048 + bsw[kst]);
                    mma16816(sacc[0][0], a0,a1,a2,a3, b0,b1);
                    mma16816(sacc[0][1], a0,a1,a2,a3, b2,b3);
                    mma16816(sacc[0][2], a0,a1,a2,a3, b4,b5);
                    mma16816(sacc[0][3], a0,a1,a2,a3, b6,b7);
                    mma16816(sacc[1][0], a4,a5,a6,a7, b0,b1);
                    mma16816(sacc[1][1], a4,a5,a6,a7, b2,b3);
                    mma16816(sacc[1][2], a4,a5,a6,a7, b4,b5);
                    mma16816(sacc[1][3], a4,a5,a6,a7, b6,b7);
                }
            }
            __syncthreads();                 // all warps done with buffer p
            if (tid == 0 && dt < NT - 1) {   // refill for next tile
                MB_EXPECT_TX(mb_ks + p * 8, 16384);
                tma2d(su + KS_OFF + p * 16384,        &tmk, (2 * p) * 64,     d0 + (dt + 1) * BD, mb_ks + p * 8);
                tma2d(su + KS_OFF + p * 16384 + 8192, &tmk, (2 * p + 1) * 64, d0 + (dt + 1) * BD, mb_ks + p * 8);
            }
        }

        // ---- epilogue: kern = 1/(xx+kk-2s+eps) -> bf16 A-frags ----
        mb_wait(mb_vs + cur * 8, pvs);       // vs + kk ready
        const float2* kk2 = (const float2*)(smb + KK_OFF + cur * 256);
        unsigned alo[2][4], ahi[2][4];
        #pragma unroll
        for (int mh = 0; mh < 2; ++mh)
            #pragma unroll
            for (int nt = 0; nt < 4; ++nt) {
                float2 kv = kk2[wd * 16 + nt * 4 + t];
                float r0 = rcpa(fmaf(-2.f, sacc[mh][nt][0], xxe[mh][0] + kv.x));
                float r1 = rcpa(fmaf(-2.f, sacc[mh][nt][1], xxe[mh][0] + kv.y));
                float r2 = rcpa(fmaf(-2.f, sacc[mh][nt][2], xxe[mh][1] + kv.x));
                float r3 = rcpa(fmaf(-2.f, sacc[mh][nt][3], xxe[mh][1] + kv.y));
                alo[mh][nt] = packbf(r0, r1);
                ahi[mh][nt] = packbf(r2, r3);
            }

        // ---- GEMM2: out[M32 x 104] += kern[M32 x k32] @ vT ----
        const uint32_t vb = su + VS_OFF + cur * 13312;
        #pragma unroll
        for (int k2 = 0; k2 < 2; ++k2) {
            #pragma unroll
            for (int j2 = 0; j2 < 6; ++j2) {
                unsigned b0,b1,b2,b3;
                ldsm4(b0,b1,b2,b3, vb + voff[j2] + vsw[k2]);
                #pragma unroll
                for (int mh = 0; mh < 2; ++mh) {
                    mma16816(oacc[mh][2 * j2],     alo[mh][2*k2], ahi[mh][2*k2],
                             alo[mh][2*k2+1], ahi[mh][2*k2+1], b0, b1);
                    mma16816(oacc[mh][2 * j2 + 1], alo[mh][2*k2], ahi[mh][2*k2],
                             alo[mh][2*k2+1], ahi[mh][2*k2+1], b2, b3);
                }
            }
            unsigned b0, b1;
            ldsm2(b0, b1, vb + 12288 + v2sw[k2]);
            #pragma unroll
            for (int mh = 0; mh < 2; ++mh)
                mma16816(oacc[mh][12], alo[mh][2*k2], ahi[mh][2*k2],
                         alo[mh][2*k2+1], ahi[mh][2*k2+1], b0, b1);
        }

        __syncthreads();                     // vs/kk consumed
        if (tid == 0 && dt + 2 < NT) {       // refill vs+kk for dt+2
            MB_EXPECT_TX(mb_vs + cur * 8, 13312 + 256);
            tma2d(su + VS_OFF + cur * 13312, &tmv, d0 + (dt + 2) * BD, 0, mb_vs + cur * 8);
            bulk1d(su + KK_OFF + cur * 256, g_kk + d0 + (dt + 2) * BD, 256, mb_vs + cur * 8);
        }
    }

    // ---- cross-wd reduction (k halves), write per-split partials ----
    __syncthreads();
    float* red = (float*)(smb + KS_OFF);
    const int rbase = (wm * 32 + lane) * 105;      // stride 105: conflict-free
    if (wd == 1) {
        #pragma unroll
        for (int mh = 0; mh < 2; ++mh)
            #pragma unroll
            for (int j = 0; j < 13; ++j)
                #pragma unroll
                for (int q = 0; q < 4; ++q)
                    red[rbase + (mh * 13 + j) * 4 + q] = oacc[mh][j][q];
    }
    __syncthreads();
    if (wd == 0) {
        #pragma unroll
        for (int mh = 0; mh < 2; ++mh)
            #pragma unroll
            for (int j = 0; j < 13; ++j)
                #pragma unroll
                for (int q = 0; q < 4; ++q)
                    oacc[mh][j][q] += red[rbase + (mh * 13 + j) * 4 + q];
        #pragma unroll
        for (int mh = 0; mh < 2; ++mh) {
            const int m0 = bm0 + wm * 32 + mh * 16 + g;
            float* p0 = g_part + ((size_t)blockIdx.y * BTOT + m0) * CP;
            float* p1 = p0 + 8 * CP;
            #pragma unroll
            for (int j = 0; j < 13; ++j) {
                const int c0 = j * 8 + 2 * t;
                *(float2*)(p0 + c0) = make_float2(oacc[mh][j][0], oacc[mh][j][1]);
                *(float2*)(p1 + c0) = make_float2(oacc[mh][j][2], oacc[mh][j][3]);
            }
        }
    }
}

// -------- final reduce over D-splits --------
__global__ void reduce_out(float* __restrict__ out) {
    int i = blockIdx.x * blockDim.x + threadIdx.x;
    if (i < BTOT * CCOLS) {
        int m = i / CCOLS;
        int c = i - m * CCOLS;
        float s = 0.f;
        #pragma unroll
        for (int ds = 0; ds < DSPLIT; ++ds)
            s += g_part[((size_t)ds * BTOT + m) * CP + c];
        out[i] = s;
    }
}

// -------- host --------
typedef CUresult (*PFN_tmEncode)(CUtensorMap*, CUtensorMapDataType, cuuint32_t,
    void*, const cuuint64_t*, const cuuint64_t*, const cuuint32_t*,
    const cuuint32_t*, CUtensorMapInterleave, CUtensorMapSwizzle,
    CUtensorMapL2promotion, CUtensorMapFloatOOBfill);

#ifndef RTLD_DEFAULT
#define RTLD_DEFAULT ((void*)0)
#endif

extern "C" void kernel_launch(void* const* d_in, const int* in_sizes, int n_in,
                              void* d_out, int out_size) {
    const float* x      = (const float*)d_in[0];   // (4096, 512)
    const float* keys   = (const float*)d_in[1];   // (16384, 512)
    const float* values = (const float*)d_in[2];   // (16384, 100)
    float* out = (float*)d_out;                    // (4096, 100)
    (void)in_sizes; (void)n_in; (void)out_size;

    void *xb_p, *kb_p, *vt_p, *xx_p, *kk_p;
    cudaGetSymbolAddress(&xb_p, g_xb);
    cudaGetSymbolAddress(&kb_p, g_kb);
    cudaGetSymbolAddress(&vt_p, g_vT);
    cudaGetSymbolAddress(&xx_p, g_xx);
    cudaGetSymbolAddress(&kk_p, g_kk);

    // Prologue
    prep_rows<<<BTOT, 128>>>(x, (__nv_bfloat16*)xb_p, (float*)xx_p);
    prep_rows<<<DTOT, 128>>>(keys, (__nv_bfloat16*)kb_p, (float*)kk_p);
    prep_vT<<<2048, 256>>>(values);

    // Tensor maps (driver API via dlsym; no -lcuda link dependency)
    void* fn = dlsym(RTLD_DEFAULT, "cuTensorMapEncodeTiled");
    if (!fn) {
        void* h = dlopen("libcuda.so.1", RTLD_NOW | RTLD_GLOBAL);
        if (h) fn = dlsym(h, "cuTensorMapEncodeTiled");
    }
    PFN_tmEncode enc = (PFN_tmEncode)fn;

    CUtensorMap tmx{}, tmk{}, tmv{};
    {
        cuuint64_t dims[2]    = {KTOT, BTOT};
        cuuint64_t strides[1] = {KTOT * 2};
        cuuint32_t box[2]     = {64, 128};
        cuuint32_t es[2]      = {1, 1};
        enc(&tmx, CU_TENSOR_MAP_DATA_TYPE_BFLOAT16, 2, xb_p, dims, strides, box, es,
            CU_TENSOR_MAP_INTERLEAVE_NONE, CU_TENSOR_MAP_SWIZZLE_128B,
            CU_TENSOR_MAP_L2_PROMOTION_L2_128B, CU_TENSOR_MAP_FLOAT_OOB_FILL_NONE);
    }
    {
        cuuint64_t dims[2]    = {KTOT, DTOT};
        cuuint64_t strides[1] = {KTOT * 2};
        cuuint32_t box[2]     = {64, 64};
        cuuint32_t es[2]      = {1, 1};
        enc(&tmk, CU_TENSOR_MAP_DATA_TYPE_BFLOAT16, 2, kb_p, dims, strides, box, es,
            CU_TENSOR_MAP_INTERLEAVE_NONE, CU_TENSOR_MAP_SWIZZLE_128B,
            CU_TENSOR_MAP_L2_PROMOTION_L2_128B, CU_TENSOR_MAP_FLOAT_OOB_FILL_NONE);
    }
    {
        cuuint64_t dims[2]    = {DTOT, CP};
        cuuint64_t strides[1] = {DTOT * 2};
        cuuint32_t box[2]     = {64, CP};
        cuuint32_t es[2]      = {1, 1};
        enc(&tmv, CU_TENSOR_MAP_DATA_TYPE_BFLOAT16, 2, vt_p, dims, strides, box, es,
            CU_TENSOR_MAP_INTERLEAVE_NONE, CU_TENSOR_MAP_SWIZZLE_128B,
            CU_TENSOR_MAP_L2_PROMOTION_L2_128B, CU_TENSOR_MAP_FLOAT_OOB_FILL_NONE);
    }

    cudaFuncSetAttribute(varkeys_main,
                         cudaFuncAttributeMaxDynamicSharedMemorySize, SMEM_BYTES);
    dim3 grid(BTOT / BM, DSPLIT);
    varkeys_main<<<grid, THREADS, SMEM_BYTES>>>(tmx, tmk, tmv);

    reduce_out<<<(BTOT * CCOLS + 255) / 256, 256>>>(out);
}